// round 3
// baseline (speedup 1.0000x reference)
#include <cuda_runtime.h>

#define BB   4
#define NN   2048
#define DIMX 512
#define HH   8
#define DHD  64
#define NKEY 2049
#define MTOT (BB*NN)

// ---------------- scratch (device globals; no allocation allowed) ----------
__device__ float g_xn[MTOT*DIMX];
__device__ float g_q [MTOT*DIMX];
__device__ float g_k [BB*NKEY*DHD];
__device__ float g_v [BB*NKEY*DHD];
__device__ float g_ao[MTOT*DIMX];
__device__ float g_o2[MTOT*DIMX];

// ---------------- LayerNorm: one block per 512-float row --------------------
__global__ __launch_bounds__(128) void ln_kernel(const float* __restrict__ x,
                                                 const float* __restrict__ g,
                                                 float* __restrict__ y) {
    int row = blockIdx.x;
    int t = threadIdx.x;
    float4 v = reinterpret_cast<const float4*>(x + (size_t)row*DIMX)[t];
    float s  = v.x + v.y + v.z + v.w;
    float s2 = v.x*v.x + v.y*v.y + v.z*v.z + v.w*v.w;
#pragma unroll
    for (int o = 16; o > 0; o >>= 1) {
        s  += __shfl_xor_sync(0xffffffffu, s,  o);
        s2 += __shfl_xor_sync(0xffffffffu, s2, o);
    }
    __shared__ float ws[4], ws2[4];
    int w = t >> 5;
    if ((t & 31) == 0) { ws[w] = s; ws2[w] = s2; }
    __syncthreads();
    float S  = ws[0]  + ws[1]  + ws[2]  + ws[3];
    float S2 = ws2[0] + ws2[1] + ws2[2] + ws2[3];
    float mu  = S * (1.0f/DIMX);
    float var = S2 * (1.0f/DIMX) - mu*mu;
    float r   = rsqrtf(var + 1e-5f);
    float4 gg = reinterpret_cast<const float4*>(g)[t];
    float4 o;
    o.x = (v.x-mu)*r*gg.x; o.y = (v.y-mu)*r*gg.y;
    o.z = (v.z-mu)*r*gg.z; o.w = (v.w-mu)*r*gg.w;
    reinterpret_cast<float4*>(y + (size_t)row*DIMX)[t] = o;
}

// ---------------- null K/V fill --------------------------------------------
__global__ void fill_null_kernel(const float* __restrict__ nkv) {
    int t = threadIdx.x;           // 256 = 4 batches * 64 dims
    int b = t >> 6, d = t & 63;
    g_k[((size_t)b*NKEY)*DHD + d] = nkv[d];
    g_v[((size_t)b*NKEY)*DHD + d] = nkv[DHD + d];
}

// ---------------- 64x64 tile SGEMM (K=512), MODE 0 plain / 1 q-scale / 2 kv-split
template<int MODE, int NC>
__global__ __launch_bounds__(256) void gemm64(const float* __restrict__ A,
                                              const float* __restrict__ B,
                                              float* __restrict__ C) {
    __shared__ float As[16][64];
    __shared__ float Bs[16][64];
    int tid = threadIdx.x;
    int tx = tid & 15, ty = tid >> 4;
    int m0 = blockIdx.y << 6, n0 = blockIdx.x << 6;
    int ar = tid >> 2,  ac = (tid & 3) << 2;
    int br = tid >> 4,  bc = (tid & 15) << 2;
    const float* Ap = A + (size_t)(m0 + ar)*DIMX + ac;
    const float* Bp = B + (size_t)br*NC + n0 + bc;
    float acc[4][4];
#pragma unroll
    for (int i = 0; i < 4; i++)
#pragma unroll
        for (int j = 0; j < 4; j++) acc[i][j] = 0.f;

    for (int k0 = 0; k0 < DIMX; k0 += 16) {
        float4 a4 = *reinterpret_cast<const float4*>(Ap + k0);
        float4 b4 = *reinterpret_cast<const float4*>(Bp + (size_t)k0*NC);
        As[ac+0][ar] = a4.x; As[ac+1][ar] = a4.y;
        As[ac+2][ar] = a4.z; As[ac+3][ar] = a4.w;
        *reinterpret_cast<float4*>(&Bs[br][bc]) = b4;
        __syncthreads();
#pragma unroll
        for (int kk = 0; kk < 16; kk++) {
            float4 av = *reinterpret_cast<const float4*>(&As[kk][ty<<2]);
            float4 bv = *reinterpret_cast<const float4*>(&Bs[kk][tx<<2]);
            float a_[4] = {av.x, av.y, av.z, av.w};
            float b_[4] = {bv.x, bv.y, bv.z, bv.w};
#pragma unroll
            for (int i = 0; i < 4; i++)
#pragma unroll
                for (int j = 0; j < 4; j++)
                    acc[i][j] = fmaf(a_[i], b_[j], acc[i][j]);
        }
        __syncthreads();
    }

#pragma unroll
    for (int i = 0; i < 4; i++) {
        int m = m0 + (ty<<2) + i;
#pragma unroll
        for (int j = 0; j < 4; j++) {
            int n = n0 + (tx<<2) + j;
            float val = acc[i][j];
            if (MODE == 0)      C[(size_t)m*NC + n] = val;
            else if (MODE == 1) C[(size_t)m*NC + n] = val * 0.125f;   // *DH^-0.5
            else {
                int b = m >> 11, nn = m & 2047;
                size_t base = ((size_t)b*NKEY + 1 + nn)*DHD;
                if (n < DHD) g_k[base + n]       = val;
                else         g_v[base + n - DHD] = val;
            }
        }
    }
}

// ---------------- flash attention: 64 queries x 64 keys tiles ---------------
// grid (32 qtiles, 8 heads, 4 batches), 256 threads, dynamic smem ~66 KB
__global__ __launch_bounds__(256) void attn_kernel(const unsigned* __restrict__ mask) {
    extern __shared__ float sm[];
    float* Qs  = sm;                       // [dh][row]  64x64
    float* Ks  = sm + 4096;                // [dh][key]  64x64
    float* Vs  = sm + 8192;                // [key][dh]  64x64
    float* Ps  = sm + 12288;               // [key][row] 64x65 (pad for conflicts)
    float* msk = sm + 12288 + 64*65;       // 64 flags

    int tid = threadIdx.x, tx = tid & 15, ty = tid >> 4;
    int m0 = blockIdx.x << 6, h = blockIdx.y, b = blockIdx.z;
    int c4 = (tid & 15) << 2, rb = (tid >> 4) << 2;

    // load Q tile, transposed to [dh][row]
#pragma unroll
    for (int i = 0; i < 4; i++) {
        int r = rb + i;
        float4 q4 = *reinterpret_cast<const float4*>(
            g_q + ((size_t)(b*NN + m0 + r))*DIMX + h*DHD + c4);
        Qs[(c4+0)*64 + r] = q4.x; Qs[(c4+1)*64 + r] = q4.y;
        Qs[(c4+2)*64 + r] = q4.z; Qs[(c4+3)*64 + r] = q4.w;
    }

    float m_[4], l_[4], o_[4][4];
#pragma unroll
    for (int i = 0; i < 4; i++) {
        m_[i] = -1e30f; l_[i] = 0.f;
#pragma unroll
        for (int j = 0; j < 4; j++) o_[i][j] = 0.f;
    }

    for (int j0 = 0; j0 < NKEY; j0 += 64) {
        // load K (transposed) and V tiles, zero-fill out of range
#pragma unroll
        for (int i = 0; i < 4; i++) {
            int key = rb + i; int jj = j0 + key;
            float4 k4 = make_float4(0,0,0,0), v4 = make_float4(0,0,0,0);
            if (jj < NKEY) {
                k4 = *reinterpret_cast<const float4*>(g_k + ((size_t)b*NKEY + jj)*DHD + c4);
                v4 = *reinterpret_cast<const float4*>(g_v + ((size_t)b*NKEY + jj)*DHD + c4);
            }
            Ks[(c4+0)*64 + key] = k4.x; Ks[(c4+1)*64 + key] = k4.y;
            Ks[(c4+2)*64 + key] = k4.z; Ks[(c4+3)*64 + key] = k4.w;
            *reinterpret_cast<float4*>(&Vs[key*64 + c4]) = v4;
        }
        if (tid < 64) {
            int jj = j0 + tid;
            bool ok = (jj < NKEY) && (jj == 0 || mask[(size_t)b*NN + jj - 1] != 0u);
            msk[tid] = ok ? 0.f : 1.f;
        }
        __syncthreads();

        // S = Q @ K^T  (per-thread 4x4)
        float s_[4][4];
#pragma unroll
        for (int i = 0; i < 4; i++)
#pragma unroll
            for (int j = 0; j < 4; j++) s_[i][j] = 0.f;
#pragma unroll 16
        for (int kk = 0; kk < 64; kk++) {
            float4 av = *reinterpret_cast<const float4*>(&Qs[kk*64 + (ty<<2)]);
            float4 bv = *reinterpret_cast<const float4*>(&Ks[kk*64 + (tx<<2)]);
            float a_[4] = {av.x, av.y, av.z, av.w};
            float b_[4] = {bv.x, bv.y, bv.z, bv.w};
#pragma unroll
            for (int i = 0; i < 4; i++)
#pragma unroll
                for (int j = 0; j < 4; j++)
                    s_[i][j] = fmaf(a_[i], b_[j], s_[i][j]);
        }

        // mask
        float mf[4];
#pragma unroll
        for (int j = 0; j < 4; j++) mf[j] = msk[(tx<<2) + j];
#pragma unroll
        for (int i = 0; i < 4; i++)
#pragma unroll
            for (int j = 0; j < 4; j++)
                if (mf[j] > 0.5f) s_[i][j] = -1e30f;

        // online softmax (16-lane row groups; lanes 0-15 share ty, 16-31 share ty+1)
#pragma unroll
        for (int i = 0; i < 4; i++) {
            float mx = fmaxf(fmaxf(s_[i][0], s_[i][1]), fmaxf(s_[i][2], s_[i][3]));
            mx = fmaxf(mx, __shfl_xor_sync(0xffffffffu, mx, 1));
            mx = fmaxf(mx, __shfl_xor_sync(0xffffffffu, mx, 2));
            mx = fmaxf(mx, __shfl_xor_sync(0xffffffffu, mx, 4));
            mx = fmaxf(mx, __shfl_xor_sync(0xffffffffu, mx, 8));
            float mn = fmaxf(m_[i], mx);
            float corr = __expf(m_[i] - mn);
            float ps = 0.f;
#pragma unroll
            for (int j = 0; j < 4; j++) {
                float p = __expf(s_[i][j] - mn);
                ps += p;
                Ps[((tx<<2)+j)*65 + (ty<<2) + i] = p;   // transposed store
            }
            ps += __shfl_xor_sync(0xffffffffu, ps, 1);
            ps += __shfl_xor_sync(0xffffffffu, ps, 2);
            ps += __shfl_xor_sync(0xffffffffu, ps, 4);
            ps += __shfl_xor_sync(0xffffffffu, ps, 8);
            l_[i] = l_[i]*corr + ps;
            m_[i] = mn;
#pragma unroll
            for (int j = 0; j < 4; j++) o_[i][j] *= corr;
        }
        __syncthreads();

        // O += P @ V
#pragma unroll 16
        for (int kk = 0; kk < 64; kk++) {
            float a_[4];
#pragma unroll
            for (int i = 0; i < 4; i++) a_[i] = Ps[kk*65 + (ty<<2) + i];
            float4 bv = *reinterpret_cast<const float4*>(&Vs[kk*64 + (tx<<2)]);
            float b_[4] = {bv.x, bv.y, bv.z, bv.w};
#pragma unroll
            for (int i = 0; i < 4; i++)
#pragma unroll
                for (int j = 0; j < 4; j++)
                    o_[i][j] = fmaf(a_[i], b_[j], o_[i][j]);
        }
        __syncthreads();
    }

    // normalize and write (b, n, h*DH + d) layout
#pragma unroll
    for (int i = 0; i < 4; i++) {
        float inv = 1.f / l_[i];
        size_t row = (size_t)(b*NN + m0 + (ty<<2) + i);
#pragma unroll
        for (int j = 0; j < 4; j++)
            g_ao[row*DIMX + h*DHD + (tx<<2) + j] = o_[i][j] * inv;
    }
}

// ---------------- launch ----------------------------------------------------
extern "C" void kernel_launch(void* const* d_in, const int* in_sizes, int n_in,
                              void* d_out, int out_size) {
    const float*    x      = (const float*)d_in[0];
    const unsigned* mask   = (const unsigned*)d_in[1];   // bool as 4-byte: !=0 works for f32/i32
    const float*    gamma  = (const float*)d_in[2];
    const float*    Wq     = (const float*)d_in[3];
    const float*    Wkv    = (const float*)d_in[4];
    const float*    nkv    = (const float*)d_in[5];
    const float*    Wout   = (const float*)d_in[6];
    const float*    ogamma = (const float*)d_in[7];
    float*          out    = (float*)d_out;

    float *xn, *q, *ao, *o2;
    cudaGetSymbolAddress((void**)&xn, g_xn);
    cudaGetSymbolAddress((void**)&q,  g_q);
    cudaGetSymbolAddress((void**)&ao, g_ao);
    cudaGetSymbolAddress((void**)&o2, g_o2);

    const int attn_smem = (12288 + 64*65 + 64) * 4;   // 66048 bytes
    cudaFuncSetAttribute(attn_kernel, cudaFuncAttributeMaxDynamicSharedMemorySize, attn_smem);

    ln_kernel<<<MTOT, 128>>>(x, gamma, xn);
    fill_null_kernel<<<1, 256>>>(nkv);
    gemm64<1, 512><<<dim3(8, 128), 256>>>(xn, Wq, q);
    gemm64<2, 128><<<dim3(2, 128), 256>>>(xn, Wkv, nullptr);
    attn_kernel<<<dim3(32, 8, 4), 256, attn_smem>>>(mask);
    gemm64<0, 512><<<dim3(8, 128), 256>>>(ao, Wout, o2);
    ln_kernel<<<MTOT, 128>>>(o2, ogamma, out);
}